// round 16
// baseline (speedup 1.0000x reference)
#include <cuda_runtime.h>
#include <cstdint>

// ---------------------------------------------------------------------------
// ChaoticLSTM: bs=64, seq=512, in=128, H=256, 4H=1024, T=512
// R16:
//   xproj_v5: R9's 64x64/4-chunk tiling + cp.async double-buffered B +
//     register-prefetched A; ONE __syncthreads per chunk.
//   lstm_rec: G=4 batch-groups per 8-CTA cluster (grid 32), same bulk+tx-mbar
//     handoff per group; per-group pointers as u32 offsets to fit RF.
// ---------------------------------------------------------------------------

typedef unsigned long long ull;

__device__ float g_xproj[32768u * 1024u];   // 128 MB scratch

__device__ __forceinline__ void fma2(ull& d, ull a, ull b) {
    asm("fma.rn.f32x2 %0, %1, %2, %0;" : "+l"(d) : "l"(a), "l"(b));
}
__device__ __forceinline__ ull splat2(float x) {
    ull r; asm("mov.b64 %0, {%1, %1};" : "=l"(r) : "f"(x)); return r;
}
__device__ __forceinline__ ull pack2(float a, float b) {
    ull r; asm("mov.b64 %0, {%1, %2};" : "=l"(r) : "f"(a), "f"(b)); return r;
}
__device__ __forceinline__ float2 unpack2(ull v) {
    float2 r; asm("mov.b64 {%0, %1}, %2;" : "=f"(r.x), "=f"(r.y) : "l"(v)); return r;
}
__device__ __forceinline__ float rcpf(float x) {
    float r; asm("rcp.approx.f32 %0, %1;" : "=f"(r) : "f"(x)); return r;
}
__device__ __forceinline__ uint32_t smem_u32(const void* p) {
    uint32_t a;
    asm("{ .reg .u64 t; cvta.to.shared.u64 t, %1; cvt.u32.u64 %0, t; }"
        : "=r"(a) : "l"(p));
    return a;
}

// ---------------------------------------------------------------------------
// Phase 1: xproj GEMM — 64x64 tile, 4 chunks, double-buffered.
// ---------------------------------------------------------------------------
__global__ __launch_bounds__(256) void xproj_v5(const float* __restrict__ X,
                                                const float* __restrict__ Wi,
                                                const float* __restrict__ Bias) {
    __shared__ __align__(16) float As_t[2][32 * 68];
    __shared__ __align__(16) float Bs[2][32 * 64];

    const int tid = threadIdx.x;
    const int m0 = blockIdx.y * 64;
    const int n0 = blockIdx.x * 64;
    const int tm = tid >> 4, tn = tid & 15;

    const float4* X4  = (const float4*)X;
    const float4* Wi4 = (const float4*)Wi;

    // helpers -----------------------------------------------------------
    const int fa0 = tid, fa1 = tid + 256;            // A float4 slots
    const int ar0 = fa0 >> 3, ak0 = fa0 & 7;
    const int ar1 = fa1 >> 3, ak1 = fa1 & 7;

    auto cpB = [&](int c, int b) {                   // cp.async B chunk c
#pragma unroll
        for (int i = 0; i < 2; ++i) {
            int f = tid + i * 256;
            int row = f >> 4, c4 = f & 15;
            uint32_t dst = smem_u32(&Bs[b][row * 64 + c4 * 4]);
            const float4* src = Wi4 + (size_t)(c * 32 + row) * 256 + (n0 >> 2) + c4;
            asm volatile("cp.async.ca.shared.global [%0], [%1], 16;"
                         :: "r"(dst), "l"(src) : "memory");
        }
        asm volatile("cp.async.commit_group;" ::: "memory");
    };

    float4 apf0, apf1;
    auto ldgA = [&](int c) {                         // A chunk c -> regs
        apf0 = X4[(size_t)(m0 + ar0) * 32 + c * 8 + ak0];
        apf1 = X4[(size_t)(m0 + ar1) * 32 + c * 8 + ak1];
    };
    auto stsA = [&](int b) {                         // regs -> As_t[b] (transpose)
        As_t[b][(ak0 * 4 + 0) * 68 + ar0] = apf0.x;
        As_t[b][(ak0 * 4 + 1) * 68 + ar0] = apf0.y;
        As_t[b][(ak0 * 4 + 2) * 68 + ar0] = apf0.z;
        As_t[b][(ak0 * 4 + 3) * 68 + ar0] = apf0.w;
        As_t[b][(ak1 * 4 + 0) * 68 + ar1] = apf1.x;
        As_t[b][(ak1 * 4 + 1) * 68 + ar1] = apf1.y;
        As_t[b][(ak1 * 4 + 2) * 68 + ar1] = apf1.z;
        As_t[b][(ak1 * 4 + 3) * 68 + ar1] = apf1.w;
    };

    // prologue: chunk 0 into buffer 0
    ldgA(0);
    cpB(0, 0);
    stsA(0);
    asm volatile("cp.async.wait_group 0;" ::: "memory");
    __syncthreads();

    ull acc[4][2];
#pragma unroll
    for (int i = 0; i < 4; ++i) { acc[i][0] = 0ull; acc[i][1] = 0ull; }

#pragma unroll
    for (int c = 0; c < 4; ++c) {
        const int p = c & 1;
        if (c < 3) { ldgA(c + 1); cpB(c + 1, p ^ 1); }

#pragma unroll
        for (int kk = 0; kk < 32; ++kk) {
            float4 a4 = *(const float4*)(&As_t[p][kk * 68 + tm * 4]);
            ulonglong2 b2 = *(const ulonglong2*)(&Bs[p][kk * 64 + tn * 4]);
            ull s;
            s = splat2(a4.x); fma2(acc[0][0], s, b2.x); fma2(acc[0][1], s, b2.y);
            s = splat2(a4.y); fma2(acc[1][0], s, b2.x); fma2(acc[1][1], s, b2.y);
            s = splat2(a4.z); fma2(acc[2][0], s, b2.x); fma2(acc[2][1], s, b2.y);
            s = splat2(a4.w); fma2(acc[3][0], s, b2.x); fma2(acc[3][1], s, b2.y);
        }

        if (c < 3) {
            stsA(p ^ 1);
            asm volatile("cp.async.wait_group 0;" ::: "memory");
            __syncthreads();
        }
    }

    float4 bias = *(const float4*)(Bias + n0 + tn * 4);
#pragma unroll
    for (int i = 0; i < 4; ++i) {
        float2 p0 = unpack2(acc[i][0]);
        float2 p1 = unpack2(acc[i][1]);
        float4 o = make_float4(p0.x + bias.x, p0.y + bias.y,
                               p1.x + bias.z, p1.y + bias.w);
        *(float4*)(g_xproj + (size_t)(m0 + tm * 4 + i) * 1024 + n0 + tn * 4) = o;
    }
}

// ---------------------------------------------------------------------------
// Phase 2: G=4 pipelined recurrence. 4 clusters x 8 CTAs x 256 thr.
// Cluster owns 16 batches; group g owns batches cb16 + g*4 .. +3.
// Per group: hbuf ping-pong (idx g*2+buf), stage block, mbar pair.
// Sender warp for group g = warp g; named barrier g+1 (producer split).
// ---------------------------------------------------------------------------
#define RSTRIDE 132
#define HBUFSZ  (8 * RSTRIDE)

__global__ __launch_bounds__(256, 1) __cluster_dims__(8, 1, 1)
void lstm_rec(const float* __restrict__ Wh, float* __restrict__ out) {
    __shared__ __align__(16) float hbuf[8][HBUFSZ];    // [g*2+buf]
    __shared__ __align__(16) float stage[8][128];      // [g*2+buf]
    __shared__ __align__(8)  ull   mbars[8];           // [g*2+buf]

    const int tid  = threadIdx.x;
    const int lane = tid & 31;
    const int w    = tid >> 5;
    const int s    = lane >> 3;
    const int cl   = lane & 7;
    const int m    = cl >> 1;
    const int q    = cl & 1;

    uint32_t rank;
    asm("mov.u32 %0, %%cluster_ctarank;" : "=r"(rank));
    const int r     = (int)rank;
    const int cb16  = (blockIdx.x >> 3) * 16;    // first batch of cluster
    const int j     = w * 4 + m;
    const int koff  = r * 32 + j;
    const int colg0 = (2 * q) * 256 + koff;
    const int colg1 = (2 * q + 1) * 256 + koff;
    const int kbase = s * 64;

    ull wreg0[32], wreg1[32];
#pragma unroll
    for (int i = 0; i < 32; ++i) {
        const float* p0 = Wh + (size_t)(kbase + 2 * i) * 1024;
        const float* p1 = Wh + (size_t)(kbase + 2 * i + 1) * 1024;
        wreg0[i] = pack2(__ldg(p0 + colg0), __ldg(p1 + colg0));
        wreg1[i] = pack2(__ldg(p0 + colg1), __ldg(p1 + colg1));
    }

    for (int i = tid; i < 8 * HBUFSZ; i += 256) ((float*)hbuf)[i] = 0.0f;
    const uint32_t lmb = smem_u32(mbars);
    if (tid == 0) {
#pragma unroll
        for (int i = 0; i < 8; ++i)
            asm volatile("mbarrier.init.shared.b64 [%0], 1;"
                         :: "r"(lmb + 8 * i) : "memory");
    }
    __syncthreads();
    asm volatile("barrier.cluster.arrive.aligned;" ::: "memory");
    asm volatile("barrier.cluster.wait.aligned;"   ::: "memory");

    // remote addresses for sender lanes (warps 0..3, lane d < 8 -> dest CTA d)
    const uint32_t hbase = smem_u32(hbuf);
    const uint32_t sbase = smem_u32(stage);
    uint32_t rem_h = 0, rem_m = 0;
    if (w < 4 && lane < 8) {
        asm("mapa.shared::cluster.u32 %0, %1, %2;" : "=r"(rem_h) : "r"(hbase), "r"(lane));
        asm("mapa.shared::cluster.u32 %0, %1, %2;" : "=r"(rem_m) : "r"(lmb),   "r"(lane));
    }

    const float am0 = q ? 2.0f : 1.0f;
    const float om0 = q ? 2.0f : 1.0f;
    const float ob0 = q ? -1.0f : 0.0f;

    const bool cellw = (q == 0);
    const int  wslot = w * 16 + s * 4 + m;

    // per-group u32 byte offsets (all < 2^28)
    uint32_t xoff0[4], xoff1[4], ooff[4];
    float    xc0[4], xc1[4], cre[4];
#pragma unroll
    for (int g = 0; g < 4; ++g) {
        const int b = cb16 + g * 4 + s;
        xoff0[g] = (uint32_t)(((size_t)b * 512 * 1024 + colg0) * 4);
        xoff1[g] = (uint32_t)(((size_t)b * 512 * 1024 + colg1) * 4);
        ooff[g]  = (uint32_t)(((size_t)b * 512 * 256 + koff) * 4);
        xc0[g] = __ldg((const float*)((const char*)g_xproj + xoff0[g]));
        xc1[g] = __ldg((const float*)((const char*)g_xproj + xoff1[g]));
        cre[g] = 0.0f;
    }

    auto dot_cell = [&](const float* hb, float xp0, float xp1,
                        float& c_) -> float {
        ull A00 = 0, A01 = 0, A02 = 0, A03 = 0;
        ull A10 = 0, A11 = 0, A12 = 0, A13 = 0;
#pragma unroll
        for (int rr = 0; rr < 2; ++rr) {
            const float* rbase = hb + (2 * s + rr) * RSTRIDE;
#pragma unroll
            for (int j4 = 0; j4 < 8; ++j4) {
                const float* qp = rbase + j4 * 16;
                ulonglong2 v0 = *(const ulonglong2*)(qp + 0);
                ulonglong2 v1 = *(const ulonglong2*)(qp + 4);
                ulonglong2 v2 = *(const ulonglong2*)(qp + 8);
                ulonglong2 v3 = *(const ulonglong2*)(qp + 12);
                const int iw = rr * 16 + j4 * 2;
                fma2(A00, wreg0[iw], v0.x); fma2(A00, wreg0[iw + 1], v0.y);
                fma2(A01, wreg0[iw], v1.x); fma2(A01, wreg0[iw + 1], v1.y);
                fma2(A02, wreg0[iw], v2.x); fma2(A02, wreg0[iw + 1], v2.y);
                fma2(A03, wreg0[iw], v3.x); fma2(A03, wreg0[iw + 1], v3.y);
                fma2(A10, wreg1[iw], v0.x); fma2(A10, wreg1[iw + 1], v0.y);
                fma2(A11, wreg1[iw], v1.x); fma2(A11, wreg1[iw + 1], v1.y);
                fma2(A12, wreg1[iw], v2.x); fma2(A12, wreg1[iw + 1], v2.y);
                fma2(A13, wreg1[iw], v3.x); fma2(A13, wreg1[iw + 1], v3.y);
            }
        }
        float2 p;
        float d00, d01, d02, d03, d10, d11, d12, d13;
        p = unpack2(A00); d00 = p.x + p.y;
        p = unpack2(A01); d01 = p.x + p.y;
        p = unpack2(A02); d02 = p.x + p.y;
        p = unpack2(A03); d03 = p.x + p.y;
        p = unpack2(A10); d10 = p.x + p.y;
        p = unpack2(A11); d11 = p.x + p.y;
        p = unpack2(A12); d12 = p.x + p.y;
        p = unpack2(A13); d13 = p.x + p.y;

        d00 += __shfl_xor_sync(0xffffffffu, d00, 8);
        d01 += __shfl_xor_sync(0xffffffffu, d01, 8);
        d02 += __shfl_xor_sync(0xffffffffu, d02, 8);
        d03 += __shfl_xor_sync(0xffffffffu, d03, 8);
        d10 += __shfl_xor_sync(0xffffffffu, d10, 8);
        d11 += __shfl_xor_sync(0xffffffffu, d11, 8);
        d12 += __shfl_xor_sync(0xffffffffu, d12, 8);
        d13 += __shfl_xor_sync(0xffffffffu, d13, 8);
        d00 += __shfl_xor_sync(0xffffffffu, d00, 16);
        d01 += __shfl_xor_sync(0xffffffffu, d01, 16);
        d02 += __shfl_xor_sync(0xffffffffu, d02, 16);
        d03 += __shfl_xor_sync(0xffffffffu, d03, 16);
        d10 += __shfl_xor_sync(0xffffffffu, d10, 16);
        d11 += __shfl_xor_sync(0xffffffffu, d11, 16);
        d12 += __shfl_xor_sync(0xffffffffu, d12, 16);
        d13 += __shfl_xor_sync(0xffffffffu, d13, 16);

        float ds0 = (s == 0) ? d00 : (s == 1) ? d01 : (s == 2) ? d02 : d03;
        float ds1 = (s == 0) ? d10 : (s == 1) ? d11 : (s == 2) ? d12 : d13;
        float gx0 = xp0 + ds0;
        float gx1 = xp1 + ds1;

        float u0 = __expf(-am0 * gx0);
        float e0 = fmaf(rcpf(1.0f + u0), om0, ob0);
        float u1 = __expf(-gx1);
        float e1 = rcpf(1.0f + u1);

        float gg = __shfl_xor_sync(0xffffffffu, e0, 1);
        float oo = __shfl_xor_sync(0xffffffffu, e1, 1);

        float hn = 0.0f;
        if (cellw) {
            c_ = fmaf(e1, c_, e0 * gg);
            float u2 = __expf(-2.0f * c_);
            float th = (1.0f - u2) * rcpf(1.0f + u2);
            hn = oo * th;
        }
        return hn;
    };

#pragma unroll 1
    for (int t = 0; t < 512; ++t) {
#pragma unroll
        for (int g = 0; g < 4; ++g) {
            if (t > 0) {
                const int u = t - 1;
                uint32_t mw = lmb + (uint32_t)((g * 2 + (u & 1)) << 3);
                uint32_t pr = (uint32_t)((u >> 1) & 1);
                asm volatile(
                    "{\n\t.reg .pred P;\n"
                    "W_%=:\n\t"
                    "mbarrier.try_wait.parity.acquire.cta.shared::cta.b64 P, [%0], %1, 0x989680;\n\t"
                    "@P bra.uni D_%=;\n\t"
                    "bra.uni W_%=;\n\t"
                    "D_%=:\n\t}"
                    :: "r"(mw), "r"(pr) : "memory");
            }
            if (tid == 0 && t < 511) {
                uint32_t ma = lmb + (uint32_t)((g * 2 + (t & 1)) << 3);
                asm volatile("mbarrier.arrive.expect_tx.shared.b64 _, [%0], %1;"
                             :: "r"(ma), "r"(4096u) : "memory");
            }

            const float* hb = (const float*)hbuf + (g * 2 + ((t + 1) & 1)) * HBUFSZ;
            float hn = dot_cell(hb, xc0[g], xc1[g], cre[g]);
            if (cellw) stage[g * 2 + (t & 1)][wslot] = hn;

            if (w == g) asm volatile("bar.sync %0, 256;" :: "r"(g + 1) : "memory");
            else        asm volatile("bar.arrive %0, 256;" :: "r"(g + 1) : "memory");

            if (t < 511 && w == g && lane < 8) {
                asm volatile("fence.proxy.async.shared::cta;" ::: "memory");
                uint32_t idx = (uint32_t)(g * 2 + (t & 1));
                uint32_t src = sbase + idx * 512u;
                uint32_t dst = rem_h + (uint32_t)((idx * HBUFSZ + r * RSTRIDE) * 4);
                uint32_t mba = rem_m + (idx << 3);
                asm volatile(
                    "cp.async.bulk.shared::cluster.shared::cta.mbarrier::complete_tx::bytes "
                    "[%0], [%1], %2, [%3];"
                    :: "r"(dst), "r"(src), "r"(512u), "r"(mba) : "memory");
            }

            if (cellw) {
                *(float*)((char*)out + ooff[g] + (uint32_t)t * 1024u) = hn;
                if (t == 511) {
                    const int b = cb16 + g * 4 + s;
                    out[8388608u + (size_t)b * 256 + koff]          = hn;
                    out[8388608u + 16384u + (size_t)b * 256 + koff] = cre[g];
                }
            }
            if (t < 511) {
                xc0[g] = __ldg((const float*)((const char*)g_xproj + xoff0[g]
                                              + (uint32_t)(t + 1) * 4096u));
                xc1[g] = __ldg((const float*)((const char*)g_xproj + xoff1[g]
                                              + (uint32_t)(t + 1) * 4096u));
            }
        }
    }
}

// ---------------------------------------------------------------------------
extern "C" void kernel_launch(void* const* d_in, const int* in_sizes, int n_in,
                              void* d_out, int out_size) {
    const float* x  = nullptr;   // 64*512*128 = 4194304
    const float* Wi = nullptr;   // 128*1024   = 131072
    const float* Wh = nullptr;   // 256*1024   = 262144
    const float* Bb = nullptr;   // 1024
    for (int i = 0; i < n_in; ++i) {
        switch (in_sizes[i]) {
            case 4194304: x  = (const float*)d_in[i]; break;
            case 131072:  Wi = (const float*)d_in[i]; break;
            case 262144:  Wh = (const float*)d_in[i]; break;
            case 1024:    Bb = (const float*)d_in[i]; break;
            default: break;
        }
    }
    float* out = (float*)d_out;
    (void)out_size;

    xproj_v5<<<dim3(16, 512), 256>>>(x, Wi, Bb);
    lstm_rec<<<32, 256>>>(Wh, out);
}

// round 17
// speedup vs baseline: 1.8663x; 1.8663x over previous
#include <cuda_runtime.h>
#include <cstdint>

// ---------------------------------------------------------------------------
// ChaoticLSTM: bs=64, seq=512, in=128, H=256, 4H=1024, T=512
// R17: combine measured bests.
//   xproj: R16's xproj_v5 (cp.async double-buffered B + reg-prefetch A,
//          measured ~219 us — best xproj).
//   rec:   R12/R14's G=2 dual-group pipelined recurrence (1296 us over 4
//          consecutive benches — proven G optimum after the G-ladder:
//          G=1 5900 cyc/iter, G=2 4750, G=4 ~9600).
// ---------------------------------------------------------------------------

typedef unsigned long long ull;

__device__ float g_xproj[32768u * 1024u];   // 128 MB scratch

__device__ __forceinline__ void fma2(ull& d, ull a, ull b) {
    asm("fma.rn.f32x2 %0, %1, %2, %0;" : "+l"(d) : "l"(a), "l"(b));
}
__device__ __forceinline__ ull splat2(float x) {
    ull r; asm("mov.b64 %0, {%1, %1};" : "=l"(r) : "f"(x)); return r;
}
__device__ __forceinline__ ull pack2(float a, float b) {
    ull r; asm("mov.b64 %0, {%1, %2};" : "=l"(r) : "f"(a), "f"(b)); return r;
}
__device__ __forceinline__ float2 unpack2(ull v) {
    float2 r; asm("mov.b64 {%0, %1}, %2;" : "=f"(r.x), "=f"(r.y) : "l"(v)); return r;
}
__device__ __forceinline__ float rcpf(float x) {
    float r; asm("rcp.approx.f32 %0, %1;" : "=f"(r) : "f"(x)); return r;
}
__device__ __forceinline__ uint32_t smem_u32(const void* p) {
    uint32_t a;
    asm("{ .reg .u64 t; cvta.to.shared.u64 t, %1; cvt.u32.u64 %0, t; }"
        : "=r"(a) : "l"(p));
    return a;
}

// ---------------------------------------------------------------------------
// Phase 1: xproj GEMM — 64x64 tile, 4 chunks, double-buffered (R16, 219 us).
// ---------------------------------------------------------------------------
__global__ __launch_bounds__(256) void xproj_v5(const float* __restrict__ X,
                                                const float* __restrict__ Wi,
                                                const float* __restrict__ Bias) {
    __shared__ __align__(16) float As_t[2][32 * 68];
    __shared__ __align__(16) float Bs[2][32 * 64];

    const int tid = threadIdx.x;
    const int m0 = blockIdx.y * 64;
    const int n0 = blockIdx.x * 64;
    const int tm = tid >> 4, tn = tid & 15;

    const float4* X4  = (const float4*)X;
    const float4* Wi4 = (const float4*)Wi;

    const int fa0 = tid, fa1 = tid + 256;
    const int ar0 = fa0 >> 3, ak0 = fa0 & 7;
    const int ar1 = fa1 >> 3, ak1 = fa1 & 7;

    auto cpB = [&](int c, int b) {
#pragma unroll
        for (int i = 0; i < 2; ++i) {
            int f = tid + i * 256;
            int row = f >> 4, c4 = f & 15;
            uint32_t dst = smem_u32(&Bs[b][row * 64 + c4 * 4]);
            const float4* src = Wi4 + (size_t)(c * 32 + row) * 256 + (n0 >> 2) + c4;
            asm volatile("cp.async.ca.shared.global [%0], [%1], 16;"
                         :: "r"(dst), "l"(src) : "memory");
        }
        asm volatile("cp.async.commit_group;" ::: "memory");
    };

    float4 apf0, apf1;
    auto ldgA = [&](int c) {
        apf0 = X4[(size_t)(m0 + ar0) * 32 + c * 8 + ak0];
        apf1 = X4[(size_t)(m0 + ar1) * 32 + c * 8 + ak1];
    };
    auto stsA = [&](int b) {
        As_t[b][(ak0 * 4 + 0) * 68 + ar0] = apf0.x;
        As_t[b][(ak0 * 4 + 1) * 68 + ar0] = apf0.y;
        As_t[b][(ak0 * 4 + 2) * 68 + ar0] = apf0.z;
        As_t[b][(ak0 * 4 + 3) * 68 + ar0] = apf0.w;
        As_t[b][(ak1 * 4 + 0) * 68 + ar1] = apf1.x;
        As_t[b][(ak1 * 4 + 1) * 68 + ar1] = apf1.y;
        As_t[b][(ak1 * 4 + 2) * 68 + ar1] = apf1.z;
        As_t[b][(ak1 * 4 + 3) * 68 + ar1] = apf1.w;
    };

    ldgA(0);
    cpB(0, 0);
    stsA(0);
    asm volatile("cp.async.wait_group 0;" ::: "memory");
    __syncthreads();

    ull acc[4][2];
#pragma unroll
    for (int i = 0; i < 4; ++i) { acc[i][0] = 0ull; acc[i][1] = 0ull; }

#pragma unroll
    for (int c = 0; c < 4; ++c) {
        const int p = c & 1;
        if (c < 3) { ldgA(c + 1); cpB(c + 1, p ^ 1); }

#pragma unroll
        for (int kk = 0; kk < 32; ++kk) {
            float4 a4 = *(const float4*)(&As_t[p][kk * 68 + tm * 4]);
            ulonglong2 b2 = *(const ulonglong2*)(&Bs[p][kk * 64 + tn * 4]);
            ull s;
            s = splat2(a4.x); fma2(acc[0][0], s, b2.x); fma2(acc[0][1], s, b2.y);
            s = splat2(a4.y); fma2(acc[1][0], s, b2.x); fma2(acc[1][1], s, b2.y);
            s = splat2(a4.z); fma2(acc[2][0], s, b2.x); fma2(acc[2][1], s, b2.y);
            s = splat2(a4.w); fma2(acc[3][0], s, b2.x); fma2(acc[3][1], s, b2.y);
        }

        if (c < 3) {
            stsA(p ^ 1);
            asm volatile("cp.async.wait_group 0;" ::: "memory");
            __syncthreads();
        }
    }

    float4 bias = *(const float4*)(Bias + n0 + tn * 4);
#pragma unroll
    for (int i = 0; i < 4; ++i) {
        float2 p0 = unpack2(acc[i][0]);
        float2 p1 = unpack2(acc[i][1]);
        float4 o = make_float4(p0.x + bias.x, p0.y + bias.y,
                               p1.x + bias.z, p1.y + bias.w);
        *(float4*)(g_xproj + (size_t)(m0 + tm * 4 + i) * 1024 + n0 + tn * 4) = o;
    }
}

// ---------------------------------------------------------------------------
// Phase 2: dual-group pipelined recurrence (R12/R14, byte-identical).
// ---------------------------------------------------------------------------
#define RSTRIDE 132
#define HBUFSZ  (8 * RSTRIDE)

__global__ __launch_bounds__(256, 1) __cluster_dims__(8, 1, 1)
void lstm_rec(const float* __restrict__ Wh, float* __restrict__ out) {
    __shared__ __align__(16) float hbuf[2][2][HBUFSZ];   // [group][buf]
    __shared__ __align__(16) float stage[2][2][128];     // [group][buf]
    __shared__ __align__(8)  ull   mbars[4];             // [group*2+buf]

    const int tid  = threadIdx.x;
    const int lane = tid & 31;
    const int w    = tid >> 5;
    const int s    = lane >> 3;
    const int cl   = lane & 7;
    const int m    = cl >> 1;
    const int q    = cl & 1;

    uint32_t rank;
    asm("mov.u32 %0, %%cluster_ctarank;" : "=r"(rank));
    const int r     = (int)rank;
    const int b0A   = (blockIdx.x >> 3) * 8;
    const int b0B   = b0A + 4;
    const int j     = w * 4 + m;
    const int koff  = r * 32 + j;
    const int colg0 = (2 * q) * 256 + koff;
    const int colg1 = (2 * q + 1) * 256 + koff;
    const int kbase = s * 64;

    ull wreg0[32], wreg1[32];
#pragma unroll
    for (int i = 0; i < 32; ++i) {
        const float* p0 = Wh + (size_t)(kbase + 2 * i) * 1024;
        const float* p1 = Wh + (size_t)(kbase + 2 * i + 1) * 1024;
        wreg0[i] = pack2(__ldg(p0 + colg0), __ldg(p1 + colg0));
        wreg1[i] = pack2(__ldg(p0 + colg1), __ldg(p1 + colg1));
    }

    for (int i = tid; i < 4 * HBUFSZ; i += 256) ((float*)hbuf)[i] = 0.0f;
    const uint32_t lmb = smem_u32(mbars);
    if (tid == 0) {
#pragma unroll
        for (int i = 0; i < 4; ++i)
            asm volatile("mbarrier.init.shared.b64 [%0], 1;"
                         :: "r"(lmb + 8 * i) : "memory");
    }
    __syncthreads();
    asm volatile("barrier.cluster.arrive.aligned;" ::: "memory");
    asm volatile("barrier.cluster.wait.aligned;"   ::: "memory");

    // remote addresses for sender lanes of warps 0 (group A) and 1 (group B)
    const uint32_t hbase = smem_u32(hbuf);
    const uint32_t sbase = smem_u32(stage);
    uint32_t rem_h = 0, rem_m = 0;
    if (w < 2 && lane < 8) {
        asm("mapa.shared::cluster.u32 %0, %1, %2;" : "=r"(rem_h) : "r"(hbase), "r"(lane));
        asm("mapa.shared::cluster.u32 %0, %1, %2;" : "=r"(rem_m) : "r"(lmb),   "r"(lane));
    }

    const float am0 = q ? 2.0f : 1.0f;
    const float om0 = q ? 2.0f : 1.0f;
    const float ob0 = q ? -1.0f : 0.0f;

    const bool cellw = (q == 0);
    const int  wslot = w * 16 + s * 4 + m;

    const float* xpA0 = g_xproj + (size_t)(b0A + s) * 512 * 1024 + colg0;
    const float* xpA1 = g_xproj + (size_t)(b0A + s) * 512 * 1024 + colg1;
    const float* xpB0 = g_xproj + (size_t)(b0B + s) * 512 * 1024 + colg0;
    const float* xpB1 = g_xproj + (size_t)(b0B + s) * 512 * 1024 + colg1;
    float* outA = out + (size_t)(b0A + s) * 512 * 256 + koff;
    float* outB = out + (size_t)(b0B + s) * 512 * 256 + koff;

    float xcA0 = __ldg(xpA0), xcA1 = __ldg(xpA1);
    float xcB0 = __ldg(xpB0), xcB1 = __ldg(xpB1);
    float creA = 0.0f, creB = 0.0f, hlA = 0.0f, hlB = 0.0f;

    auto dot_cell = [&](const float* hb, float xp0, float xp1,
                        float& cre) -> float {
        ull A00 = 0, A01 = 0, A02 = 0, A03 = 0;
        ull A10 = 0, A11 = 0, A12 = 0, A13 = 0;
#pragma unroll
        for (int rr = 0; rr < 2; ++rr) {
            const float* rbase = hb + (2 * s + rr) * RSTRIDE;
#pragma unroll
            for (int j4 = 0; j4 < 8; ++j4) {
                const float* qp = rbase + j4 * 16;
                ulonglong2 v0 = *(const ulonglong2*)(qp + 0);
                ulonglong2 v1 = *(const ulonglong2*)(qp + 4);
                ulonglong2 v2 = *(const ulonglong2*)(qp + 8);
                ulonglong2 v3 = *(const ulonglong2*)(qp + 12);
                const int iw = rr * 16 + j4 * 2;
                fma2(A00, wreg0[iw], v0.x); fma2(A00, wreg0[iw + 1], v0.y);
                fma2(A01, wreg0[iw], v1.x); fma2(A01, wreg0[iw + 1], v1.y);
                fma2(A02, wreg0[iw], v2.x); fma2(A02, wreg0[iw + 1], v2.y);
                fma2(A03, wreg0[iw], v3.x); fma2(A03, wreg0[iw + 1], v3.y);
                fma2(A10, wreg1[iw], v0.x); fma2(A10, wreg1[iw + 1], v0.y);
                fma2(A11, wreg1[iw], v1.x); fma2(A11, wreg1[iw + 1], v1.y);
                fma2(A12, wreg1[iw], v2.x); fma2(A12, wreg1[iw + 1], v2.y);
                fma2(A13, wreg1[iw], v3.x); fma2(A13, wreg1[iw + 1], v3.y);
            }
        }
        float2 p;
        float d00, d01, d02, d03, d10, d11, d12, d13;
        p = unpack2(A00); d00 = p.x + p.y;
        p = unpack2(A01); d01 = p.x + p.y;
        p = unpack2(A02); d02 = p.x + p.y;
        p = unpack2(A03); d03 = p.x + p.y;
        p = unpack2(A10); d10 = p.x + p.y;
        p = unpack2(A11); d11 = p.x + p.y;
        p = unpack2(A12); d12 = p.x + p.y;
        p = unpack2(A13); d13 = p.x + p.y;

        d00 += __shfl_xor_sync(0xffffffffu, d00, 8);
        d01 += __shfl_xor_sync(0xffffffffu, d01, 8);
        d02 += __shfl_xor_sync(0xffffffffu, d02, 8);
        d03 += __shfl_xor_sync(0xffffffffu, d03, 8);
        d10 += __shfl_xor_sync(0xffffffffu, d10, 8);
        d11 += __shfl_xor_sync(0xffffffffu, d11, 8);
        d12 += __shfl_xor_sync(0xffffffffu, d12, 8);
        d13 += __shfl_xor_sync(0xffffffffu, d13, 8);
        d00 += __shfl_xor_sync(0xffffffffu, d00, 16);
        d01 += __shfl_xor_sync(0xffffffffu, d01, 16);
        d02 += __shfl_xor_sync(0xffffffffu, d02, 16);
        d03 += __shfl_xor_sync(0xffffffffu, d03, 16);
        d10 += __shfl_xor_sync(0xffffffffu, d10, 16);
        d11 += __shfl_xor_sync(0xffffffffu, d11, 16);
        d12 += __shfl_xor_sync(0xffffffffu, d12, 16);
        d13 += __shfl_xor_sync(0xffffffffu, d13, 16);

        float ds0 = (s == 0) ? d00 : (s == 1) ? d01 : (s == 2) ? d02 : d03;
        float ds1 = (s == 0) ? d10 : (s == 1) ? d11 : (s == 2) ? d12 : d13;
        float gx0 = xp0 + ds0;
        float gx1 = xp1 + ds1;

        float u0 = __expf(-am0 * gx0);
        float e0 = fmaf(rcpf(1.0f + u0), om0, ob0);
        float u1 = __expf(-gx1);
        float e1 = rcpf(1.0f + u1);

        float gg = __shfl_xor_sync(0xffffffffu, e0, 1);
        float oo = __shfl_xor_sync(0xffffffffu, e1, 1);

        float hn = 0.0f;
        if (cellw) {
            cre = fmaf(e1, cre, e0 * gg);
            float u2 = __expf(-2.0f * cre);
            float th = (1.0f - u2) * rcpf(1.0f + u2);
            hn = oo * th;
        }
        return hn;
    };

    auto wait_mbar = [&](int g, int u) {
        uint32_t mw = lmb + (uint32_t)((g * 2 + (u & 1)) << 3);
        uint32_t pr = (uint32_t)((u >> 1) & 1);
        asm volatile(
            "{\n\t.reg .pred P;\n"
            "W_%=:\n\t"
            "mbarrier.try_wait.parity.acquire.cta.shared::cta.b64 P, [%0], %1, 0x989680;\n\t"
            "@P bra.uni D_%=;\n\t"
            "bra.uni W_%=;\n\t"
            "D_%=:\n\t}"
            :: "r"(mw), "r"(pr) : "memory");
    };

    auto send_group = [&](int g, int t) {   // caller gates on warp & lane
        asm volatile("fence.proxy.async.shared::cta;" ::: "memory");
        uint32_t idx = (uint32_t)(g * 2 + (t & 1));
        uint32_t src = sbase + idx * 512u;
        uint32_t dst = rem_h + (uint32_t)((idx * HBUFSZ + r * RSTRIDE) * 4);
        uint32_t mba = rem_m + (idx << 3);
        asm volatile(
            "cp.async.bulk.shared::cluster.shared::cta.mbarrier::complete_tx::bytes "
            "[%0], [%1], %2, [%3];"
            :: "r"(dst), "r"(src), "r"(512u), "r"(mba) : "memory");
    };

#pragma unroll 1
    for (int t = 0; t < 512; ++t) {
        // ================= group A =================
        if (t > 0) wait_mbar(0, t - 1);
        if (tid == 0 && t < 511) {
            uint32_t ma = lmb + (uint32_t)((t & 1) << 3);
            asm volatile("mbarrier.arrive.expect_tx.shared.b64 _, [%0], %1;"
                         :: "r"(ma), "r"(4096u) : "memory");
        }
        {
            const float* hb = (const float*)hbuf + ((t + 1) & 1) * HBUFSZ;
            float hn = dot_cell(hb, xcA0, xcA1, creA);
            if (cellw) { hlA = hn; stage[0][t & 1][wslot] = hn; }

            if (w == 0) asm volatile("bar.sync 1, 256;" ::: "memory");
            else        asm volatile("bar.arrive 1, 256;" ::: "memory");

            if (t < 511 && w == 0 && lane < 8) send_group(0, t);

            if (cellw) outA[(size_t)t * 256] = hn;
            if (t < 511) { xcA0 = __ldg(xpA0 + (size_t)(t + 1) * 1024);
                           xcA1 = __ldg(xpA1 + (size_t)(t + 1) * 1024); }
        }

        // ================= group B =================
        if (t > 0) wait_mbar(1, t - 1);
        if (tid == 0 && t < 511) {
            uint32_t ma = lmb + (uint32_t)((2 + (t & 1)) << 3);
            asm volatile("mbarrier.arrive.expect_tx.shared.b64 _, [%0], %1;"
                         :: "r"(ma), "r"(4096u) : "memory");
        }
        {
            const float* hb = (const float*)hbuf + (2 + ((t + 1) & 1)) * HBUFSZ;
            float hn = dot_cell(hb, xcB0, xcB1, creB);
            if (cellw) { hlB = hn; stage[1][t & 1][wslot] = hn; }

            if (w == 1) asm volatile("bar.sync 2, 256;" ::: "memory");
            else        asm volatile("bar.arrive 2, 256;" ::: "memory");

            // B-send from warp 1 (the warp that bar.sync'd barrier 2)
            if (t < 511 && w == 1 && lane < 8) send_group(1, t);

            if (cellw) outB[(size_t)t * 256] = hn;
            if (t < 511) { xcB0 = __ldg(xpB0 + (size_t)(t + 1) * 1024);
                           xcB1 = __ldg(xpB1 + (size_t)(t + 1) * 1024); }
        }
    }

    if (cellw) {
        out[8388608u + (size_t)(b0A + s) * 256 + koff]          = hlA;
        out[8388608u + 16384u + (size_t)(b0A + s) * 256 + koff] = creA;
        out[8388608u + (size_t)(b0B + s) * 256 + koff]          = hlB;
        out[8388608u + 16384u + (size_t)(b0B + s) * 256 + koff] = creB;
    }
}

// ---------------------------------------------------------------------------
extern "C" void kernel_launch(void* const* d_in, const int* in_sizes, int n_in,
                              void* d_out, int out_size) {
    const float* x  = nullptr;   // 64*512*128 = 4194304
    const float* Wi = nullptr;   // 128*1024   = 131072
    const float* Wh = nullptr;   // 256*1024   = 262144
    const float* Bb = nullptr;   // 1024
    for (int i = 0; i < n_in; ++i) {
        switch (in_sizes[i]) {
            case 4194304: x  = (const float*)d_in[i]; break;
            case 131072:  Wi = (const float*)d_in[i]; break;
            case 262144:  Wh = (const float*)d_in[i]; break;
            case 1024:    Bb = (const float*)d_in[i]; break;
            default: break;
        }
    }
    float* out = (float*)d_out;
    (void)out_size;

    xproj_v5<<<dim3(16, 512), 256>>>(x, Wi, Bb);
    lstm_rec<<<64, 256>>>(Wh, out);
}